// round 1
// baseline (speedup 1.0000x reference)
#include <cuda_runtime.h>
#include <math.h>

#define B_  2
#define T_  2048
#define D_  2048
#define NH_ 16
#define KH_ 4
#define H_  128

// Scratch (allocation-free rule: __device__ globals)
__device__ float g_q[B_*T_*NH_*H_];    // 32 MB  (b,t,n,h)
__device__ float g_k[B_*T_*KH_*H_];    //  8 MB  (b,t,k,h)
__device__ float g_v[B_*T_*KH_*H_];    //  8 MB  (b,t,k,h)
__device__ float g_attn[B_*T_*NH_*H_]; // 32 MB  (b,t,n,h)

// ---------------------------------------------------------------------------
// SGEMM: C[M,Nc] = A[M,Kd] @ B[Kd,Nc], all row-major, dims multiple of 128/8
// 128x128 block tile, K-tile 8, 256 threads, 8x8 per thread
// ---------------------------------------------------------------------------
__global__ __launch_bounds__(256)
void sgemm128(const float* __restrict__ A, const float* __restrict__ B,
              float* __restrict__ C, int M, int Nc, int Kd) {
    __shared__ float As[8][128];
    __shared__ float Bs[8][128];
    int tid = threadIdx.x;
    int brow = blockIdx.y * 128, bcol = blockIdx.x * 128;

    int a_row = tid >> 1;
    int a_k4  = (tid & 1) * 4;
    int b_k   = tid >> 5;
    int b_c4  = (tid & 31) * 4;
    int ty = tid >> 4, tx = tid & 15;

    float acc[8][8];
#pragma unroll
    for (int i = 0; i < 8; i++)
#pragma unroll
        for (int j = 0; j < 8; j++) acc[i][j] = 0.f;

    for (int k0 = 0; k0 < Kd; k0 += 8) {
        float4 av = *(const float4*)&A[(size_t)(brow + a_row) * Kd + k0 + a_k4];
        As[a_k4 + 0][a_row] = av.x;
        As[a_k4 + 1][a_row] = av.y;
        As[a_k4 + 2][a_row] = av.z;
        As[a_k4 + 3][a_row] = av.w;
        *(float4*)&Bs[b_k][b_c4] =
            *(const float4*)&B[(size_t)(k0 + b_k) * Nc + bcol + b_c4];
        __syncthreads();
#pragma unroll
        for (int kk = 0; kk < 8; kk++) {
            float ar[8], br[8];
            *(float4*)(ar)     = *(const float4*)&As[kk][ty * 8];
            *(float4*)(ar + 4) = *(const float4*)&As[kk][ty * 8 + 4];
            *(float4*)(br)     = *(const float4*)&Bs[kk][tx * 8];
            *(float4*)(br + 4) = *(const float4*)&Bs[kk][tx * 8 + 4];
#pragma unroll
            for (int i = 0; i < 8; i++)
#pragma unroll
                for (int j = 0; j < 8; j++)
                    acc[i][j] += ar[i] * br[j];
        }
        __syncthreads();
    }
#pragma unroll
    for (int i = 0; i < 8; i++) {
        float4* dst = (float4*)&C[(size_t)(brow + ty * 8 + i) * Nc + bcol + tx * 8];
        dst[0] = make_float4(acc[i][0], acc[i][1], acc[i][2], acc[i][3]);
        dst[1] = make_float4(acc[i][4], acc[i][5], acc[i][6], acc[i][7]);
    }
}

// ---------------------------------------------------------------------------
// RoPE, in place. One block per token, 64 threads (i = rotary pair index),
// loops over heads (same angle across heads). Double sincos for accuracy.
// ---------------------------------------------------------------------------
__global__ void rope_kernel(float* __restrict__ x, const int* __restrict__ pos,
                            int heads) {
    int token = blockIdx.x;   // b*T + t
    int i = threadIdx.x;      // 0..63
    // timescale = 10000^(i/64)
    double ts = exp(((double)i / 64.0) * 9.210340371976182736); // ln(1e4)
    float p = (float)pos[token];
    float angf = p / (float)ts;   // mimic reference's f32 angle
    double s_, c_;
    sincos((double)angf, &s_, &c_);
    float s = (float)s_, c = (float)c_;
    float* base = x + (size_t)token * heads * H_;
#pragma unroll 4
    for (int n = 0; n < heads; n++) {
        float x1 = base[n * H_ + i];
        float x2 = base[n * H_ + i + 64];
        base[n * H_ + i]      = x1 * c - x2 * s;
        base[n * H_ + i + 64] = x2 * c + x1 * s;
    }
}

// ---------------------------------------------------------------------------
// Flash attention, causal, GQA (kv head = n/4).
// Block: 256 threads, q tile 64, kv tile 64. Online softmax.
// smem: Qs 64x128 | Ks 64x129 (pad) | Vs 64x128 | S 64x65 (pad) | stats
// O accumulator in registers: warp w owns rows 8w..8w+7,
// lane l owns h columns {l, l+32, l+64, l+96}.
// ---------------------------------------------------------------------------
#define FA_SMEM ((64*128 + 64*129 + 64*128 + 64*65 + 3*64) * 4)

__global__ __launch_bounds__(256, 1)
void flash_kernel(const float* __restrict__ q, const float* __restrict__ k,
                  const float* __restrict__ v, float* __restrict__ o) {
    extern __shared__ float sm[];
    float* Qs    = sm;                 // 64*128
    float* Ks    = Qs + 64 * 128;      // 64*129
    float* Vs    = Ks + 64 * 129;      // 64*128
    float* S     = Vs + 64 * 128;      // 64*65
    float* row_m = S + 64 * 65;
    float* row_l = row_m + 64;
    float* row_a = row_l + 64;

    int qt = (int)gridDim.x - 1 - (int)blockIdx.x;  // big tiles first
    int n  = blockIdx.y;
    int b  = blockIdx.z;
    int kh = n >> 2;
    int tid = threadIdx.x;
    int q0 = qt * 64;
    const float scale = 0.08838834764831845f; // 1/sqrt(128)

    // load Q tile (coalesced float4)
#pragma unroll
    for (int u = 0; u < 8; u++) {
        int f = tid + 256 * u;
        int r = f >> 5, hc = (f & 31) * 4;
        *(float4*)(Qs + r * 128 + hc) =
            *(const float4*)(q + (((size_t)(b * T_ + q0 + r) * NH_ + n) << 7) + hc);
    }
    if (tid < 64) { row_m[tid] = -1e30f; row_l[tid] = 0.f; }
    __syncthreads();

    int ty = tid >> 4, tx = tid & 15;       // S compute layout
    int w  = tid >> 5, l  = tid & 31;       // PV layout
    float acc[8][4];
#pragma unroll
    for (int r = 0; r < 8; r++)
#pragma unroll
        for (int j = 0; j < 4; j++) acc[r][j] = 0.f;

    for (int jt = 0; jt <= qt; jt++) {
        int s0 = jt * 64;
        // load K (scatter into padded rows) and V (float4)
#pragma unroll
        for (int u = 0; u < 8; u++) {
            int f = tid + 256 * u;
            int r = f >> 5, hc = (f & 31) * 4;
            size_t gofs = (((size_t)(b * T_ + s0 + r) * KH_ + kh) << 7) + hc;
            float4 kv = *(const float4*)(k + gofs);
            Ks[r * 129 + hc + 0] = kv.x;
            Ks[r * 129 + hc + 1] = kv.y;
            Ks[r * 129 + hc + 2] = kv.z;
            Ks[r * 129 + hc + 3] = kv.w;
            *(float4*)(Vs + r * 128 + hc) = *(const float4*)(v + gofs);
        }
        __syncthreads();

        // S = scale * Q K^T with causal mask; each thread a 4x4 microtile
        {
            float sacc[4][4];
#pragma unroll
            for (int i = 0; i < 4; i++)
#pragma unroll
                for (int j = 0; j < 4; j++) sacc[i][j] = 0.f;
            for (int hh = 0; hh < 128; hh += 4) {
                float4 qv[4];
#pragma unroll
                for (int i = 0; i < 4; i++)
                    qv[i] = *(const float4*)(Qs + (ty * 4 + i) * 128 + hh);
#pragma unroll
                for (int j = 0; j < 4; j++) {
                    const float* kp = Ks + (tx * 4 + j) * 129 + hh;
                    float k0 = kp[0], k1 = kp[1], k2 = kp[2], k3 = kp[3];
#pragma unroll
                    for (int i = 0; i < 4; i++)
                        sacc[i][j] += qv[i].x * k0 + qv[i].y * k1 +
                                      qv[i].z * k2 + qv[i].w * k3;
                }
            }
#pragma unroll
            for (int i = 0; i < 4; i++) {
                int qrow = q0 + ty * 4 + i;
#pragma unroll
                for (int j = 0; j < 4; j++) {
                    int krow = s0 + tx * 4 + j;
                    S[(ty * 4 + i) * 65 + tx * 4 + j] =
                        (krow <= qrow) ? sacc[i][j] * scale : -1e30f;
                }
            }
        }
        __syncthreads();

        // online softmax: 4 threads per row
        {
            int r = tid >> 2, g = tid & 3;
            float old_m = row_m[r];
            float mloc = -1e30f;
#pragma unroll
            for (int c = g; c < 64; c += 4)
                mloc = fmaxf(mloc, S[r * 65 + c]);
            mloc = fmaxf(mloc, __shfl_xor_sync(0xffffffffu, mloc, 1));
            mloc = fmaxf(mloc, __shfl_xor_sync(0xffffffffu, mloc, 2));
            float new_m = fmaxf(old_m, mloc);
            float lloc = 0.f;
#pragma unroll
            for (int c = g; c < 64; c += 4) {
                float pexp = __expf(S[r * 65 + c] - new_m);
                S[r * 65 + c] = pexp;
                lloc += pexp;
            }
            lloc += __shfl_xor_sync(0xffffffffu, lloc, 1);
            lloc += __shfl_xor_sync(0xffffffffu, lloc, 2);
            if (g == 0) {
                float alpha = __expf(old_m - new_m);
                row_a[r] = alpha;
                row_l[r] = row_l[r] * alpha + lloc;
                row_m[r] = new_m;
            }
        }
        __syncthreads();

        // O = O*alpha + P V
        {
#pragma unroll
            for (int r = 0; r < 8; r++) {
                float a = row_a[8 * w + r];
#pragma unroll
                for (int j = 0; j < 4; j++) acc[r][j] *= a;
            }
            for (int c = 0; c < 64; c++) {
                float v0 = Vs[c * 128 + l];
                float v1 = Vs[c * 128 + l + 32];
                float v2 = Vs[c * 128 + l + 64];
                float v3 = Vs[c * 128 + l + 96];
#pragma unroll
                for (int r = 0; r < 8; r++) {
                    float pp = S[(8 * w + r) * 65 + c];
                    acc[r][0] += pp * v0;
                    acc[r][1] += pp * v1;
                    acc[r][2] += pp * v2;
                    acc[r][3] += pp * v3;
                }
            }
        }
        __syncthreads();
    }

    // epilogue: normalize and store (b,t,n,h)
#pragma unroll
    for (int r = 0; r < 8; r++) {
        float inv = 1.0f / row_l[8 * w + r];
        size_t base = ((size_t)(b * T_ + q0 + 8 * w + r) * NH_ + n) << 7;
        o[base + l]      = acc[r][0] * inv;
        o[base + l + 32] = acc[r][1] * inv;
        o[base + l + 64] = acc[r][2] * inv;
        o[base + l + 96] = acc[r][3] * inv;
    }
}

// ---------------------------------------------------------------------------
extern "C" void kernel_launch(void* const* d_in, const int* in_sizes, int n_in,
                              void* d_out, int out_size) {
    const float* Xq   = (const float*)d_in[0];
    const float* Xkv  = (const float*)d_in[1];
    const int*   qpos = (const int*)  d_in[2];
    const int*   kpos = (const int*)  d_in[3];
    const float* Wq   = (const float*)d_in[4];
    const float* Wk   = (const float*)d_in[5];
    const float* Wv   = (const float*)d_in[6];
    const float* Wo   = (const float*)d_in[7];
    float* out = (float*)d_out;

    float *pq, *pk, *pv, *pa;
    cudaGetSymbolAddress((void**)&pq, g_q);
    cudaGetSymbolAddress((void**)&pk, g_k);
    cudaGetSymbolAddress((void**)&pv, g_v);
    cudaGetSymbolAddress((void**)&pa, g_attn);

    const int M = B_ * T_;  // 4096

    // projections
    sgemm128<<<dim3(D_ / 128, M / 128), 256>>>(Xq,  Wq, pq, M, NH_ * H_, D_);
    sgemm128<<<dim3((KH_ * H_) / 128, M / 128), 256>>>(Xkv, Wk, pk, M, KH_ * H_, D_);
    sgemm128<<<dim3((KH_ * H_) / 128, M / 128), 256>>>(Xkv, Wv, pv, M, KH_ * H_, D_);

    // rope (in place)
    rope_kernel<<<M, 64>>>(pq, qpos, NH_);
    rope_kernel<<<M, 64>>>(pk, kpos, KH_);

    // flash attention
    cudaFuncSetAttribute(flash_kernel,
                         cudaFuncAttributeMaxDynamicSharedMemorySize, FA_SMEM);
    flash_kernel<<<dim3(T_ / 64, NH_, B_), 256, FA_SMEM>>>(pq, pk, pv, pa);

    // output projection
    sgemm128<<<dim3(D_ / 128, M / 128), 256>>>(pa, Wo, out, M, D_, NH_ * H_);
}

// round 2
// speedup vs baseline: 1.8094x; 1.8094x over previous
#include <cuda_runtime.h>
#include <math.h>
#include <stdint.h>

#define B_  2
#define T_  2048
#define D_  2048
#define NH_ 16
#define KH_ 4
#define H_  128

// Scratch (allocation-free rule: __device__ globals)
__device__ float g_q[B_*T_*NH_*H_];    // 32 MB  (b,t,n,h)
__device__ float g_k[B_*T_*KH_*H_];    //  8 MB  (b,t,k,h)
__device__ float g_v[B_*T_*KH_*H_];    //  8 MB  (b,t,k,h)
__device__ float g_attn[B_*T_*NH_*H_]; // 32 MB  (b,t,n,h)

// ---------------------------------------------------------------------------
// TF32 tensor-core GEMM: C[M,Nc] = A[M,Kd] @ B[Kd,Nc], row-major.
// 128x128 block tile, K-tile 16, 256 threads (8 warps in 2x4 grid),
// warptile 64x32 = 4x4 grid of m16n8k8 mma fragments.
// cp.async double-buffered smem. Conflict-free fragment LDS:
//   As [m][k] stride 20, Bs [k][n] stride 132.
// ---------------------------------------------------------------------------
#define AST 20
#define BST 132

__device__ __forceinline__ uint32_t f2tf32(float f) {
    uint32_t u;
    asm("cvt.rna.tf32.f32 %0, %1;" : "=r"(u) : "f"(f));
    return u;
}

__device__ __forceinline__ void cpasync16(void* dst, const void* src) {
    uint32_t d = (uint32_t)__cvta_generic_to_shared(dst);
    asm volatile("cp.async.cg.shared.global [%0], [%1], 16;\n" :: "r"(d), "l"(src));
}

__device__ __forceinline__ void mma_tf32(float* c, const uint32_t* a, const uint32_t* b) {
    asm volatile(
        "mma.sync.aligned.m16n8k8.row.col.f32.tf32.tf32.f32 "
        "{%0,%1,%2,%3}, {%4,%5,%6,%7}, {%8,%9}, {%0,%1,%2,%3};\n"
        : "+f"(c[0]), "+f"(c[1]), "+f"(c[2]), "+f"(c[3])
        : "r"(a[0]), "r"(a[1]), "r"(a[2]), "r"(a[3]),
          "r"(b[0]), "r"(b[1]));
}

__global__ __launch_bounds__(256)
void gemm_tf32(const float* __restrict__ A, const float* __restrict__ B,
               float* __restrict__ C, int M, int Nc, int Kd) {
    __shared__ float As[2][128 * AST];
    __shared__ float Bs[2][16 * BST];
    int tid  = threadIdx.x;
    int brow = blockIdx.y * 128, bcol = blockIdx.x * 128;
    int warp = tid >> 5, lane = tid & 31;
    int mw = (warp >> 2) * 64, nw = (warp & 3) * 32;
    int lr = lane >> 2, lc = lane & 3;

    float acc[4][4][4];
#pragma unroll
    for (int mi = 0; mi < 4; mi++)
#pragma unroll
        for (int ni = 0; ni < 4; ni++)
#pragma unroll
            for (int j = 0; j < 4; j++) acc[mi][ni][j] = 0.f;

    const int nkt = Kd >> 4;

    // stage loader: 512 16B chunks each for A and B, 2 per thread
    auto load_stage = [&](int kt, int buf) {
        int k0 = kt * 16;
#pragma unroll
        for (int u = 0; u < 2; u++) {
            int c = tid + 256 * u;
            int arow = c >> 2, ak4 = (c & 3) * 4;
            cpasync16(&As[buf][arow * AST + ak4],
                      &A[(size_t)(brow + arow) * Kd + k0 + ak4]);
            int bkr = c >> 5, bn4 = (c & 31) * 4;
            cpasync16(&Bs[buf][bkr * BST + bn4],
                      &B[(size_t)(k0 + bkr) * Nc + bcol + bn4]);
        }
    };

    load_stage(0, 0);
    asm volatile("cp.async.commit_group;\n");

    for (int kt = 0; kt < nkt; kt++) {
        int buf = kt & 1;
        if (kt + 1 < nkt) {
            load_stage(kt + 1, buf ^ 1);
            asm volatile("cp.async.commit_group;\n");
            asm volatile("cp.async.wait_group 1;\n");
        } else {
            asm volatile("cp.async.wait_group 0;\n");
        }
        __syncthreads();

#pragma unroll
        for (int ks = 0; ks < 16; ks += 8) {
            uint32_t af[4][4], bf[4][2];
#pragma unroll
            for (int mi = 0; mi < 4; mi++) {
                const float* p = &As[buf][(mw + mi * 16 + lr) * AST + ks + lc];
                af[mi][0] = f2tf32(p[0]);
                af[mi][1] = f2tf32(p[8 * AST]);
                af[mi][2] = f2tf32(p[4]);
                af[mi][3] = f2tf32(p[8 * AST + 4]);
            }
#pragma unroll
            for (int ni = 0; ni < 4; ni++) {
                const float* p = &Bs[buf][(ks + lc) * BST + nw + ni * 8 + lr];
                bf[ni][0] = f2tf32(p[0]);
                bf[ni][1] = f2tf32(p[4 * BST]);
            }
#pragma unroll
            for (int mi = 0; mi < 4; mi++)
#pragma unroll
                for (int ni = 0; ni < 4; ni++)
                    mma_tf32(acc[mi][ni], af[mi], bf[ni]);
        }
        __syncthreads();
    }

    // epilogue: c0,c1 at (row, 2*lc), c2,c3 at (row+8, 2*lc)
#pragma unroll
    for (int mi = 0; mi < 4; mi++) {
#pragma unroll
        for (int ni = 0; ni < 4; ni++) {
            int r0 = brow + mw + mi * 16 + lr;
            int cc = bcol + nw + ni * 8 + lc * 2;
            *(float2*)&C[(size_t)r0 * Nc + cc] =
                make_float2(acc[mi][ni][0], acc[mi][ni][1]);
            *(float2*)&C[(size_t)(r0 + 8) * Nc + cc] =
                make_float2(acc[mi][ni][2], acc[mi][ni][3]);
        }
    }
}

// ---------------------------------------------------------------------------
// RoPE, in place. One block per token, 64 threads (i = rotary pair index).
// ---------------------------------------------------------------------------
__global__ void rope_kernel(float* __restrict__ x, const int* __restrict__ pos,
                            int heads) {
    int token = blockIdx.x;   // b*T + t
    int i = threadIdx.x;      // 0..63
    double ts = exp(((double)i / 64.0) * 9.210340371976182736); // ln(1e4)
    float p = (float)pos[token];
    float angf = p / (float)ts;
    double s_, c_;
    sincos((double)angf, &s_, &c_);
    float s = (float)s_, c = (float)c_;
    float* base = x + (size_t)token * heads * H_;
#pragma unroll 4
    for (int n = 0; n < heads; n++) {
        float x1 = base[n * H_ + i];
        float x2 = base[n * H_ + i + 64];
        base[n * H_ + i]      = x1 * c - x2 * s;
        base[n * H_ + i + 64] = x2 * c + x1 * s;
    }
}

// ---------------------------------------------------------------------------
// Flash attention, causal, GQA (kv head = n/4). (unchanged from R1)
// ---------------------------------------------------------------------------
#define FA_SMEM ((64*128 + 64*129 + 64*128 + 64*65 + 3*64) * 4)

__global__ __launch_bounds__(256, 1)
void flash_kernel(const float* __restrict__ q, const float* __restrict__ k,
                  const float* __restrict__ v, float* __restrict__ o) {
    extern __shared__ float sm[];
    float* Qs    = sm;                 // 64*128
    float* Ks    = Qs + 64 * 128;      // 64*129
    float* Vs    = Ks + 64 * 129;      // 64*128
    float* S     = Vs + 64 * 128;      // 64*65
    float* row_m = S + 64 * 65;
    float* row_l = row_m + 64;
    float* row_a = row_l + 64;

    int qt = (int)gridDim.x - 1 - (int)blockIdx.x;  // big tiles first
    int n  = blockIdx.y;
    int b  = blockIdx.z;
    int kh = n >> 2;
    int tid = threadIdx.x;
    int q0 = qt * 64;
    const float scale = 0.08838834764831845f; // 1/sqrt(128)

#pragma unroll
    for (int u = 0; u < 8; u++) {
        int f = tid + 256 * u;
        int r = f >> 5, hc = (f & 31) * 4;
        *(float4*)(Qs + r * 128 + hc) =
            *(const float4*)(q + (((size_t)(b * T_ + q0 + r) * NH_ + n) << 7) + hc);
    }
    if (tid < 64) { row_m[tid] = -1e30f; row_l[tid] = 0.f; }
    __syncthreads();

    int ty = tid >> 4, tx = tid & 15;
    int w  = tid >> 5, l  = tid & 31;
    float acc[8][4];
#pragma unroll
    for (int r = 0; r < 8; r++)
#pragma unroll
        for (int j = 0; j < 4; j++) acc[r][j] = 0.f;

    for (int jt = 0; jt <= qt; jt++) {
        int s0 = jt * 64;
#pragma unroll
        for (int u = 0; u < 8; u++) {
            int f = tid + 256 * u;
            int r = f >> 5, hc = (f & 31) * 4;
            size_t gofs = (((size_t)(b * T_ + s0 + r) * KH_ + kh) << 7) + hc;
            float4 kv = *(const float4*)(k + gofs);
            Ks[r * 129 + hc + 0] = kv.x;
            Ks[r * 129 + hc + 1] = kv.y;
            Ks[r * 129 + hc + 2] = kv.z;
            Ks[r * 129 + hc + 3] = kv.w;
            *(float4*)(Vs + r * 128 + hc) = *(const float4*)(v + gofs);
        }
        __syncthreads();

        {
            float sacc[4][4];
#pragma unroll
            for (int i = 0; i < 4; i++)
#pragma unroll
                for (int j = 0; j < 4; j++) sacc[i][j] = 0.f;
            for (int hh = 0; hh < 128; hh += 4) {
                float4 qv[4];
#pragma unroll
                for (int i = 0; i < 4; i++)
                    qv[i] = *(const float4*)(Qs + (ty * 4 + i) * 128 + hh);
#pragma unroll
                for (int j = 0; j < 4; j++) {
                    const float* kp = Ks + (tx * 4 + j) * 129 + hh;
                    float k0 = kp[0], k1 = kp[1], k2 = kp[2], k3 = kp[3];
#pragma unroll
                    for (int i = 0; i < 4; i++)
                        sacc[i][j] += qv[i].x * k0 + qv[i].y * k1 +
                                      qv[i].z * k2 + qv[i].w * k3;
                }
            }
#pragma unroll
            for (int i = 0; i < 4; i++) {
                int qrow = q0 + ty * 4 + i;
#pragma unroll
                for (int j = 0; j < 4; j++) {
                    int krow = s0 + tx * 4 + j;
                    S[(ty * 4 + i) * 65 + tx * 4 + j] =
                        (krow <= qrow) ? sacc[i][j] * scale : -1e30f;
                }
            }
        }
        __syncthreads();

        {
            int r = tid >> 2, g = tid & 3;
            float old_m = row_m[r];
            float mloc = -1e30f;
#pragma unroll
            for (int c = g; c < 64; c += 4)
                mloc = fmaxf(mloc, S[r * 65 + c]);
            mloc = fmaxf(mloc, __shfl_xor_sync(0xffffffffu, mloc, 1));
            mloc = fmaxf(mloc, __shfl_xor_sync(0xffffffffu, mloc, 2));
            float new_m = fmaxf(old_m, mloc);
            float lloc = 0.f;
#pragma unroll
            for (int c = g; c < 64; c += 4) {
                float pexp = __expf(S[r * 65 + c] - new_m);
                S[r * 65 + c] = pexp;
                lloc += pexp;
            }
            lloc += __shfl_xor_sync(0xffffffffu, lloc, 1);
            lloc += __shfl_xor_sync(0xffffffffu, lloc, 2);
            if (g == 0) {
                float alpha = __expf(old_m - new_m);
                row_a[r] = alpha;
                row_l[r] = row_l[r] * alpha + lloc;
                row_m[r] = new_m;
            }
        }
        __syncthreads();

        {
#pragma unroll
            for (int r = 0; r < 8; r++) {
                float a = row_a[8 * w + r];
#pragma unroll
                for (int j = 0; j < 4; j++) acc[r][j] *= a;
            }
            for (int c = 0; c < 64; c++) {
                float v0 = Vs[c * 128 + l];
                float v1 = Vs[c * 128 + l + 32];
                float v2 = Vs[c * 128 + l + 64];
                float v3 = Vs[c * 128 + l + 96];
#pragma unroll
                for (int r = 0; r < 8; r++) {
                    float pp = S[(8 * w + r) * 65 + c];
                    acc[r][0] += pp * v0;
                    acc[r][1] += pp * v1;
                    acc[r][2] += pp * v2;
                    acc[r][3] += pp * v3;
                }
            }
        }
        __syncthreads();
    }

#pragma unroll
    for (int r = 0; r < 8; r++) {
        float inv = 1.0f / row_l[8 * w + r];
        size_t base = ((size_t)(b * T_ + q0 + 8 * w + r) * NH_ + n) << 7;
        o[base + l]      = acc[r][0] * inv;
        o[base + l + 32] = acc[r][1] * inv;
        o[base + l + 64] = acc[r][2] * inv;
        o[base + l + 96] = acc[r][3] * inv;
    }
}

// ---------------------------------------------------------------------------
extern "C" void kernel_launch(void* const* d_in, const int* in_sizes, int n_in,
                              void* d_out, int out_size) {
    const float* Xq   = (const float*)d_in[0];
    const float* Xkv  = (const float*)d_in[1];
    const int*   qpos = (const int*)  d_in[2];
    const int*   kpos = (const int*)  d_in[3];
    const float* Wq   = (const float*)d_in[4];
    const float* Wk   = (const float*)d_in[5];
    const float* Wv   = (const float*)d_in[6];
    const float* Wo   = (const float*)d_in[7];
    float* out = (float*)d_out;

    float *pq, *pk, *pv, *pa;
    cudaGetSymbolAddress((void**)&pq, g_q);
    cudaGetSymbolAddress((void**)&pk, g_k);
    cudaGetSymbolAddress((void**)&pv, g_v);
    cudaGetSymbolAddress((void**)&pa, g_attn);

    const int M = B_ * T_;  // 4096

    // projections (tf32 tensor cores)
    gemm_tf32<<<dim3(D_ / 128, M / 128), 256>>>(Xq,  Wq, pq, M, NH_ * H_, D_);
    gemm_tf32<<<dim3((KH_ * H_) / 128, M / 128), 256>>>(Xkv, Wk, pk, M, KH_ * H_, D_);
    gemm_tf32<<<dim3((KH_ * H_) / 128, M / 128), 256>>>(Xkv, Wv, pv, M, KH_ * H_, D_);

    // rope (in place)
    rope_kernel<<<M, 64>>>(pq, qpos, NH_);
    rope_kernel<<<M, 64>>>(pk, kpos, KH_);

    // flash attention (fp32, unchanged)
    cudaFuncSetAttribute(flash_kernel,
                         cudaFuncAttributeMaxDynamicSharedMemorySize, FA_SMEM);
    flash_kernel<<<dim3(T_ / 64, NH_, B_), 256, FA_SMEM>>>(pq, pk, pv, pa);

    // output projection (tf32 tensor cores)
    gemm_tf32<<<dim3(D_ / 128, M / 128), 256>>>(pa, Wo, out, M, D_, NH_ * H_);
}

// round 3
// speedup vs baseline: 3.5115x; 1.9407x over previous
#include <cuda_runtime.h>
#include <math.h>
#include <stdint.h>

#define B_  2
#define T_  2048
#define D_  2048
#define NH_ 16
#define KH_ 4
#define H_  128

// Scratch (allocation-free rule: __device__ globals)
__device__ float g_q[B_*T_*NH_*H_];    // 32 MB  (b,t,n,h)
__device__ float g_k[B_*T_*KH_*H_];    //  8 MB  (b,t,k,h)
__device__ float g_v[B_*T_*KH_*H_];    //  8 MB  (b,t,k,h)
__device__ float g_attn[B_*T_*NH_*H_]; // 32 MB  (b,t,n,h)

__device__ __forceinline__ uint32_t f2tf32(float f) {
    uint32_t u;
    asm("cvt.rna.tf32.f32 %0, %1;" : "=r"(u) : "f"(f));
    return u;
}

__device__ __forceinline__ void cpasync16(void* dst, const void* src) {
    uint32_t d = (uint32_t)__cvta_generic_to_shared(dst);
    asm volatile("cp.async.cg.shared.global [%0], [%1], 16;\n" :: "r"(d), "l"(src));
}

__device__ __forceinline__ void mma_tf32(float* c, const uint32_t* a, const uint32_t* b) {
    asm volatile(
        "mma.sync.aligned.m16n8k8.row.col.f32.tf32.tf32.f32 "
        "{%0,%1,%2,%3}, {%4,%5,%6,%7}, {%8,%9}, {%0,%1,%2,%3};\n"
        : "+f"(c[0]), "+f"(c[1]), "+f"(c[2]), "+f"(c[3])
        : "r"(a[0]), "r"(a[1]), "r"(a[2]), "r"(a[3]),
          "r"(b[0]), "r"(b[1]));
}

// ---------------------------------------------------------------------------
// TF32 tensor-core GEMM (unchanged from R2)
// ---------------------------------------------------------------------------
#define AST 20
#define BST 132

__global__ __launch_bounds__(256)
void gemm_tf32(const float* __restrict__ A, const float* __restrict__ B,
               float* __restrict__ C, int M, int Nc, int Kd) {
    __shared__ float As[2][128 * AST];
    __shared__ float Bs[2][16 * BST];
    int tid  = threadIdx.x;
    int brow = blockIdx.y * 128, bcol = blockIdx.x * 128;
    int warp = tid >> 5, lane = tid & 31;
    int mw = (warp >> 2) * 64, nw = (warp & 3) * 32;
    int lr = lane >> 2, lc = lane & 3;

    float acc[4][4][4];
#pragma unroll
    for (int mi = 0; mi < 4; mi++)
#pragma unroll
        for (int ni = 0; ni < 4; ni++)
#pragma unroll
            for (int j = 0; j < 4; j++) acc[mi][ni][j] = 0.f;

    const int nkt = Kd >> 4;

    auto load_stage = [&](int kt, int buf) {
        int k0 = kt * 16;
#pragma unroll
        for (int u = 0; u < 2; u++) {
            int c = tid + 256 * u;
            int arow = c >> 2, ak4 = (c & 3) * 4;
            cpasync16(&As[buf][arow * AST + ak4],
                      &A[(size_t)(brow + arow) * Kd + k0 + ak4]);
            int bkr = c >> 5, bn4 = (c & 31) * 4;
            cpasync16(&Bs[buf][bkr * BST + bn4],
                      &B[(size_t)(k0 + bkr) * Nc + bcol + bn4]);
        }
    };

    load_stage(0, 0);
    asm volatile("cp.async.commit_group;\n");

    for (int kt = 0; kt < nkt; kt++) {
        int buf = kt & 1;
        if (kt + 1 < nkt) {
            load_stage(kt + 1, buf ^ 1);
            asm volatile("cp.async.commit_group;\n");
            asm volatile("cp.async.wait_group 1;\n");
        } else {
            asm volatile("cp.async.wait_group 0;\n");
        }
        __syncthreads();

#pragma unroll
        for (int ks = 0; ks < 16; ks += 8) {
            uint32_t af[4][4], bf[4][2];
#pragma unroll
            for (int mi = 0; mi < 4; mi++) {
                const float* p = &As[buf][(mw + mi * 16 + lr) * AST + ks + lc];
                af[mi][0] = f2tf32(p[0]);
                af[mi][1] = f2tf32(p[8 * AST]);
                af[mi][2] = f2tf32(p[4]);
                af[mi][3] = f2tf32(p[8 * AST + 4]);
            }
#pragma unroll
            for (int ni = 0; ni < 4; ni++) {
                const float* p = &Bs[buf][(ks + lc) * BST + nw + ni * 8 + lr];
                bf[ni][0] = f2tf32(p[0]);
                bf[ni][1] = f2tf32(p[4 * BST]);
            }
#pragma unroll
            for (int mi = 0; mi < 4; mi++)
#pragma unroll
                for (int ni = 0; ni < 4; ni++)
                    mma_tf32(acc[mi][ni], af[mi], bf[ni]);
        }
        __syncthreads();
    }

#pragma unroll
    for (int mi = 0; mi < 4; mi++) {
#pragma unroll
        for (int ni = 0; ni < 4; ni++) {
            int r0 = brow + mw + mi * 16 + lr;
            int cc = bcol + nw + ni * 8 + lc * 2;
            *(float2*)&C[(size_t)r0 * Nc + cc] =
                make_float2(acc[mi][ni][0], acc[mi][ni][1]);
            *(float2*)&C[(size_t)(r0 + 8) * Nc + cc] =
                make_float2(acc[mi][ni][2], acc[mi][ni][3]);
        }
    }
}

// ---------------------------------------------------------------------------
// RoPE (unchanged)
// ---------------------------------------------------------------------------
__global__ void rope_kernel(float* __restrict__ x, const int* __restrict__ pos,
                            int heads) {
    int token = blockIdx.x;
    int i = threadIdx.x;
    double ts = exp(((double)i / 64.0) * 9.210340371976182736);
    float p = (float)pos[token];
    float angf = p / (float)ts;
    double s_, c_;
    sincos((double)angf, &s_, &c_);
    float s = (float)s_, c = (float)c_;
    float* base = x + (size_t)token * heads * H_;
#pragma unroll 4
    for (int n = 0; n < heads; n++) {
        float x1 = base[n * H_ + i];
        float x2 = base[n * H_ + i + 64];
        base[n * H_ + i]      = x1 * c - x2 * s;
        base[n * H_ + i + 64] = x2 * c + x1 * s;
    }
}

// ---------------------------------------------------------------------------
// Tensor-core flash attention (tf32), causal, GQA.
// Block = 256 threads (8 warps), Q tile 128 (warp w owns rows w*16..+16),
// KV tile 64. Q held as tf32 A-frags in regs; K/V stored tf32 in smem;
// softmax in register C-frags via quad shuffles; P via per-warp smem.
//   Ks stride 132 (4lr+lc banks), Vs stride 136 (8lc+lr), Ps stride 68.
// ---------------------------------------------------------------------------
#define FST 132
#define VST 136
#define PST 68
#define FA2_SMEM ((64*FST + 64*VST + 8*16*PST) * 4)

__global__ __launch_bounds__(256, 1)
void flash_tc(const float* __restrict__ q, const float* __restrict__ k,
              const float* __restrict__ v, float* __restrict__ o) {
    extern __shared__ uint32_t sm_u[];
    uint32_t* Ks = sm_u;                 // 64 x FST (tf32 bits; also Q staging as float)
    uint32_t* Vs = Ks + 64 * FST;        // 64 x VST (tf32 bits)
    uint32_t* Ps = Vs + 64 * VST;        // 8 warps x 16 x PST (tf32 bits)

    int qt = (int)gridDim.x - 1 - (int)blockIdx.x;
    int n  = blockIdx.y;
    int b  = blockIdx.z;
    int kh = n >> 2;
    int tid = threadIdx.x, warp = tid >> 5, lane = tid & 31;
    int lr = lane >> 2, lc = lane & 3;
    int q0 = qt * 128;
    const float scale = 0.08838834764831845f; // 1/sqrt(128)

    // ---- load Q fragments (two staging passes through Ks region) ----
    uint32_t qf[16][4];
#pragma unroll
    for (int pass = 0; pass < 2; pass++) {
        float* Kf = (float*)Ks;
#pragma unroll
        for (int u = 0; u < 8; u++) {
            int f = tid + 256 * u;
            int r = f >> 5, hc = (f & 31) * 4;
            float4 qv = *(const float4*)(q +
                (((size_t)(b * T_ + q0 + pass * 64 + r) * NH_ + n) << 7) + hc);
            qv.x *= scale; qv.y *= scale; qv.z *= scale; qv.w *= scale;
            *(float4*)(Kf + r * FST + hc) = qv;
        }
        __syncthreads();
        if ((warp >> 2) == pass) {
            int mr = (warp & 3) * 16;
#pragma unroll
            for (int hs = 0; hs < 16; hs++) {
                const float* p = Kf + (mr + lr) * FST + hs * 8 + lc;
                qf[hs][0] = f2tf32(p[0]);
                qf[hs][1] = f2tf32(p[8 * FST]);
                qf[hs][2] = f2tf32(p[4]);
                qf[hs][3] = f2tf32(p[8 * FST + 4]);
            }
        }
        __syncthreads();
    }

    float m_[2] = {-1e30f, -1e30f};
    float l_[2] = {0.f, 0.f};
    float oacc[16][4];
#pragma unroll
    for (int ns = 0; ns < 16; ns++)
#pragma unroll
        for (int j = 0; j < 4; j++) oacc[ns][j] = 0.f;

    int row0 = q0 + warp * 16 + lr;   // this thread's first q row
    int njt = 2 * qt + 2;

    for (int jt = 0; jt < njt; jt++) {
        int s0 = jt * 64;
        // ---- load K,V tile, converting to tf32 bits ----
#pragma unroll
        for (int u = 0; u < 8; u++) {
            int f = tid + 256 * u;
            int r = f >> 5, hc = (f & 31) * 4;
            size_t gofs = (((size_t)(b * T_ + s0 + r) * KH_ + kh) << 7) + hc;
            float4 kv = *(const float4*)(k + gofs);
            uint4 kb = make_uint4(f2tf32(kv.x), f2tf32(kv.y), f2tf32(kv.z), f2tf32(kv.w));
            *(uint4*)(Ks + r * FST + hc) = kb;
            float4 vv = *(const float4*)(v + gofs);
            uint4 vb = make_uint4(f2tf32(vv.x), f2tf32(vv.y), f2tf32(vv.z), f2tf32(vv.w));
            *(uint4*)(Vs + r * VST + hc) = vb;
        }
        __syncthreads();

        // ---- S = Q K^T (scaled) ----
        float s_[8][4];
#pragma unroll
        for (int ns = 0; ns < 8; ns++)
#pragma unroll
            for (int j = 0; j < 4; j++) s_[ns][j] = 0.f;
#pragma unroll
        for (int hs = 0; hs < 16; hs++) {
#pragma unroll
            for (int ns = 0; ns < 8; ns++) {
                const uint32_t* p = Ks + (ns * 8 + lr) * FST + hs * 8 + lc;
                uint32_t bf[2] = {p[0], p[4]};
                mma_tf32(s_[ns], qf[hs], bf);
            }
        }

        // ---- causal mask (only last two kv tiles can cross diagonal) ----
        if (jt >= 2 * qt) {
#pragma unroll
            for (int ns = 0; ns < 8; ns++) {
                int col = s0 + ns * 8 + 2 * lc;
                if (col > row0)     s_[ns][0] = -1e30f;
                if (col + 1 > row0) s_[ns][1] = -1e30f;
                if (col > row0 + 8)     s_[ns][2] = -1e30f;
                if (col + 1 > row0 + 8) s_[ns][3] = -1e30f;
            }
        }

        // ---- online softmax in registers ----
        float mx0 = -1e30f, mx1 = -1e30f;
#pragma unroll
        for (int ns = 0; ns < 8; ns++) {
            mx0 = fmaxf(mx0, fmaxf(s_[ns][0], s_[ns][1]));
            mx1 = fmaxf(mx1, fmaxf(s_[ns][2], s_[ns][3]));
        }
        mx0 = fmaxf(mx0, __shfl_xor_sync(0xffffffffu, mx0, 1));
        mx0 = fmaxf(mx0, __shfl_xor_sync(0xffffffffu, mx0, 2));
        mx1 = fmaxf(mx1, __shfl_xor_sync(0xffffffffu, mx1, 1));
        mx1 = fmaxf(mx1, __shfl_xor_sync(0xffffffffu, mx1, 2));
        float mn0 = fmaxf(m_[0], mx0), mn1 = fmaxf(m_[1], mx1);
        float a0 = __expf(m_[0] - mn0), a1 = __expf(m_[1] - mn1);
        float sum0 = 0.f, sum1 = 0.f;
        uint32_t* Pw = Ps + warp * 16 * PST;
#pragma unroll
        for (int ns = 0; ns < 8; ns++) {
            float p0 = __expf(s_[ns][0] - mn0);
            float p1 = __expf(s_[ns][1] - mn0);
            float p2 = __expf(s_[ns][2] - mn1);
            float p3 = __expf(s_[ns][3] - mn1);
            sum0 += p0 + p1;
            sum1 += p2 + p3;
            *(uint2*)(Pw + lr * PST + ns * 8 + 2 * lc) =
                make_uint2(f2tf32(p0), f2tf32(p1));
            *(uint2*)(Pw + (lr + 8) * PST + ns * 8 + 2 * lc) =
                make_uint2(f2tf32(p2), f2tf32(p3));
        }
        sum0 += __shfl_xor_sync(0xffffffffu, sum0, 1);
        sum0 += __shfl_xor_sync(0xffffffffu, sum0, 2);
        sum1 += __shfl_xor_sync(0xffffffffu, sum1, 1);
        sum1 += __shfl_xor_sync(0xffffffffu, sum1, 2);
        l_[0] = l_[0] * a0 + sum0;
        l_[1] = l_[1] * a1 + sum1;
        m_[0] = mn0; m_[1] = mn1;

        // rescale O
#pragma unroll
        for (int ns = 0; ns < 16; ns++) {
            oacc[ns][0] *= a0; oacc[ns][1] *= a0;
            oacc[ns][2] *= a1; oacc[ns][3] *= a1;
        }
        __syncwarp();

        // ---- O += P V ----
#pragma unroll
        for (int ks = 0; ks < 8; ks++) {
            const uint32_t* pp = Pw + lr * PST + ks * 8 + lc;
            uint32_t af[4] = {pp[0], pp[8 * PST], pp[4], pp[8 * PST + 4]};
#pragma unroll
            for (int ns = 0; ns < 16; ns++) {
                const uint32_t* vp = Vs + (ks * 8 + lc) * VST + ns * 8 + lr;
                uint32_t bf[2] = {vp[0], vp[4 * VST]};
                mma_tf32(oacc[ns], af, bf);
            }
        }
        __syncthreads();
    }

    // ---- epilogue: normalize + store (b,t,n,h) ----
    float inv0 = 1.f / l_[0], inv1 = 1.f / l_[1];
    size_t base0 = (((size_t)(b * T_ + row0) * NH_ + n) << 7);
    size_t base1 = (((size_t)(b * T_ + row0 + 8) * NH_ + n) << 7);
#pragma unroll
    for (int ns = 0; ns < 16; ns++) {
        int cc = ns * 8 + 2 * lc;
        *(float2*)(o + base0 + cc) = make_float2(oacc[ns][0] * inv0, oacc[ns][1] * inv0);
        *(float2*)(o + base1 + cc) = make_float2(oacc[ns][2] * inv1, oacc[ns][3] * inv1);
    }
}

// ---------------------------------------------------------------------------
extern "C" void kernel_launch(void* const* d_in, const int* in_sizes, int n_in,
                              void* d_out, int out_size) {
    const float* Xq   = (const float*)d_in[0];
    const float* Xkv  = (const float*)d_in[1];
    const int*   qpos = (const int*)  d_in[2];
    const int*   kpos = (const int*)  d_in[3];
    const float* Wq   = (const float*)d_in[4];
    const float* Wk   = (const float*)d_in[5];
    const float* Wv   = (const float*)d_in[6];
    const float* Wo   = (const float*)d_in[7];
    float* out = (float*)d_out;

    float *pq, *pk, *pv, *pa;
    cudaGetSymbolAddress((void**)&pq, g_q);
    cudaGetSymbolAddress((void**)&pk, g_k);
    cudaGetSymbolAddress((void**)&pv, g_v);
    cudaGetSymbolAddress((void**)&pa, g_attn);

    const int M = B_ * T_;  // 4096

    gemm_tf32<<<dim3(D_ / 128, M / 128), 256>>>(Xq,  Wq, pq, M, NH_ * H_, D_);
    gemm_tf32<<<dim3((KH_ * H_) / 128, M / 128), 256>>>(Xkv, Wk, pk, M, KH_ * H_, D_);
    gemm_tf32<<<dim3((KH_ * H_) / 128, M / 128), 256>>>(Xkv, Wv, pv, M, KH_ * H_, D_);

    rope_kernel<<<M, 64>>>(pq, qpos, NH_);
    rope_kernel<<<M, 64>>>(pk, kpos, KH_);

    cudaFuncSetAttribute(flash_tc,
                         cudaFuncAttributeMaxDynamicSharedMemorySize, FA2_SMEM);
    flash_tc<<<dim3(T_ / 128, NH_, B_), 256, FA2_SMEM>>>(pq, pk, pv, pa);

    gemm_tf32<<<dim3(D_ / 128, M / 128), 256>>>(pa, Wo, out, M, D_, NH_ * H_);
}

// round 4
// speedup vs baseline: 3.6835x; 1.0490x over previous
#include <cuda_runtime.h>
#include <math.h>
#include <stdint.h>

#define B_  2
#define T_  2048
#define D_  2048
#define NH_ 16
#define KH_ 4
#define H_  128

// Scratch (allocation-free rule: __device__ globals)
__device__ float g_q[B_*T_*NH_*H_];    // 32 MB  (b,t,n,h)  -> tf32 bits after rope
__device__ float g_k[B_*T_*KH_*H_];    //  8 MB  (b,t,k,h)  -> tf32 bits after rope
__device__ float g_v[B_*T_*KH_*H_];    //  8 MB  (b,t,k,h)  -> tf32 bits after cvt
__device__ float g_attn[B_*T_*NH_*H_]; // 32 MB  (b,t,n,h)  fp32

__device__ __forceinline__ uint32_t f2tf32(float f) {
    uint32_t u;
    asm("cvt.rna.tf32.f32 %0, %1;" : "=r"(u) : "f"(f));
    return u;
}

__device__ __forceinline__ void cpasync16(void* dst, const void* src) {
    uint32_t d = (uint32_t)__cvta_generic_to_shared(dst);
    asm volatile("cp.async.cg.shared.global [%0], [%1], 16;\n" :: "r"(d), "l"(src));
}

__device__ __forceinline__ void mma_tf32(float* c, const uint32_t* a, const uint32_t* b) {
    asm volatile(
        "mma.sync.aligned.m16n8k8.row.col.f32.tf32.tf32.f32 "
        "{%0,%1,%2,%3}, {%4,%5,%6,%7}, {%8,%9}, {%0,%1,%2,%3};\n"
        : "+f"(c[0]), "+f"(c[1]), "+f"(c[2]), "+f"(c[3])
        : "r"(a[0]), "r"(a[1]), "r"(a[2]), "r"(a[3]),
          "r"(b[0]), "r"(b[1]));
}

// ---------------------------------------------------------------------------
// TF32 tensor-core GEMM body (shared by plain + fused-KV kernels)
// ---------------------------------------------------------------------------
#define AST 20
#define BST 132

__device__ __forceinline__
void gemm_body(const float* __restrict__ A, const float* __restrict__ B,
               float* __restrict__ C, int M, int Nc, int Kd) {
    __shared__ float As[2][128 * AST];
    __shared__ float Bs[2][16 * BST];
    int tid  = threadIdx.x;
    int brow = blockIdx.y * 128, bcol = blockIdx.x * 128;
    int warp = tid >> 5, lane = tid & 31;
    int mw = (warp >> 2) * 64, nw = (warp & 3) * 32;
    int lr = lane >> 2, lc = lane & 3;

    float acc[4][4][4];
#pragma unroll
    for (int mi = 0; mi < 4; mi++)
#pragma unroll
        for (int ni = 0; ni < 4; ni++)
#pragma unroll
            for (int j = 0; j < 4; j++) acc[mi][ni][j] = 0.f;

    const int nkt = Kd >> 4;

    auto load_stage = [&](int kt, int buf) {
        int k0 = kt * 16;
#pragma unroll
        for (int u = 0; u < 2; u++) {
            int c = tid + 256 * u;
            int arow = c >> 2, ak4 = (c & 3) * 4;
            cpasync16(&As[buf][arow * AST + ak4],
                      &A[(size_t)(brow + arow) * Kd + k0 + ak4]);
            int bkr = c >> 5, bn4 = (c & 31) * 4;
            cpasync16(&Bs[buf][bkr * BST + bn4],
                      &B[(size_t)(k0 + bkr) * Nc + bcol + bn4]);
        }
    };

    load_stage(0, 0);
    asm volatile("cp.async.commit_group;\n");

    for (int kt = 0; kt < nkt; kt++) {
        int buf = kt & 1;
        if (kt + 1 < nkt) {
            load_stage(kt + 1, buf ^ 1);
            asm volatile("cp.async.commit_group;\n");
            asm volatile("cp.async.wait_group 1;\n");
        } else {
            asm volatile("cp.async.wait_group 0;\n");
        }
        __syncthreads();

#pragma unroll
        for (int ks = 0; ks < 16; ks += 8) {
            uint32_t af[4][4], bf[4][2];
#pragma unroll
            for (int mi = 0; mi < 4; mi++) {
                const float* p = &As[buf][(mw + mi * 16 + lr) * AST + ks + lc];
                af[mi][0] = f2tf32(p[0]);
                af[mi][1] = f2tf32(p[8 * AST]);
                af[mi][2] = f2tf32(p[4]);
                af[mi][3] = f2tf32(p[8 * AST + 4]);
            }
#pragma unroll
            for (int ni = 0; ni < 4; ni++) {
                const float* p = &Bs[buf][(ks + lc) * BST + nw + ni * 8 + lr];
                bf[ni][0] = f2tf32(p[0]);
                bf[ni][1] = f2tf32(p[4 * BST]);
            }
#pragma unroll
            for (int mi = 0; mi < 4; mi++)
#pragma unroll
                for (int ni = 0; ni < 4; ni++)
                    mma_tf32(acc[mi][ni], af[mi], bf[ni]);
        }
        __syncthreads();
    }

#pragma unroll
    for (int mi = 0; mi < 4; mi++) {
#pragma unroll
        for (int ni = 0; ni < 4; ni++) {
            int r0 = brow + mw + mi * 16 + lr;
            int cc = bcol + nw + ni * 8 + lc * 2;
            *(float2*)&C[(size_t)r0 * Nc + cc] =
                make_float2(acc[mi][ni][0], acc[mi][ni][1]);
            *(float2*)&C[(size_t)(r0 + 8) * Nc + cc] =
                make_float2(acc[mi][ni][2], acc[mi][ni][3]);
        }
    }
}

__global__ __launch_bounds__(256)
void gemm_tf32(const float* __restrict__ A, const float* __restrict__ B,
               float* __restrict__ C, int M, int Nc, int Kd) {
    gemm_body(A, B, C, M, Nc, Kd);
}

// fused K+V projection: blockIdx.z selects weight/output pair
__global__ __launch_bounds__(256)
void gemm_tf32_kv(const float* __restrict__ A,
                  const float* __restrict__ B0, const float* __restrict__ B1,
                  float* __restrict__ C0, float* __restrict__ C1,
                  int M, int Nc, int Kd) {
    gemm_body(A, blockIdx.z ? B1 : B0, blockIdx.z ? C1 : C0, M, Nc, Kd);
}

// ---------------------------------------------------------------------------
// RoPE + optional scale + tf32-bit conversion, in place.
// ---------------------------------------------------------------------------
__global__ void rope_cvt_kernel(float* __restrict__ x, const int* __restrict__ pos,
                                int heads, float scale) {
    int token = blockIdx.x;
    int i = threadIdx.x;  // 0..63
    double ts = exp(((double)i / 64.0) * 9.210340371976182736);
    float p = (float)pos[token];
    float angf = p / (float)ts;
    double s_, c_;
    sincos((double)angf, &s_, &c_);
    float s = (float)s_, c = (float)c_;
    float* base = x + (size_t)token * heads * H_;
    uint32_t* baseb = (uint32_t*)base;
#pragma unroll 4
    for (int n = 0; n < heads; n++) {
        float x1 = base[n * H_ + i];
        float x2 = base[n * H_ + i + 64];
        baseb[n * H_ + i]      = f2tf32((x1 * c - x2 * s) * scale);
        baseb[n * H_ + i + 64] = f2tf32((x2 * c + x1 * s) * scale);
    }
}

// plain fp32 -> tf32-bits conversion, in place (for V)
__global__ void cvt_tf32_kernel(float* __restrict__ x) {
    int i = blockIdx.x * 256 + threadIdx.x;
    float4 vv = ((const float4*)x)[i];
    ((uint4*)x)[i] = make_uint4(f2tf32(vv.x), f2tf32(vv.y),
                                f2tf32(vv.z), f2tf32(vv.w));
}

// ---------------------------------------------------------------------------
// Tensor-core flash attention (tf32), causal, GQA.
// Q/K/V arrive as tf32 bit patterns (Q pre-scaled). K/V tiles are cp.async
// double-buffered; no conversion anywhere in the hot loop.
// ---------------------------------------------------------------------------
#define FST 132
#define VST 136
#define PST 68
#define FA3_SMEM ((2*64*FST + 2*64*VST + 8*16*PST) * 4)

__global__ __launch_bounds__(256, 1)
void flash_tc(const uint32_t* __restrict__ q, const uint32_t* __restrict__ k,
              const uint32_t* __restrict__ v, float* __restrict__ o) {
    extern __shared__ uint32_t sm_u[];
    uint32_t* Ks = sm_u;                    // [2][64*FST]
    uint32_t* Vs = Ks + 2 * 64 * FST;       // [2][64*VST]
    uint32_t* Ps = Vs + 2 * 64 * VST;       // 8 warps x 16 x PST

    int qt = (int)gridDim.x - 1 - (int)blockIdx.x;  // big tiles first
    int n  = blockIdx.y;
    int b  = blockIdx.z;
    int kh = n >> 2;
    int tid = threadIdx.x, warp = tid >> 5, lane = tid & 31;
    int lr = lane >> 2, lc = lane & 3;
    int q0 = qt * 128;

    // ---- load Q fragments (two staging passes through Ks[0], raw bits) ----
    uint32_t qf[16][4];
#pragma unroll
    for (int pass = 0; pass < 2; pass++) {
#pragma unroll
        for (int u = 0; u < 8; u++) {
            int f = tid + 256 * u;
            int r = f >> 5, hc = (f & 31) * 4;
            *(uint4*)(Ks + r * FST + hc) = *(const uint4*)(q +
                (((size_t)(b * T_ + q0 + pass * 64 + r) * NH_ + n) << 7) + hc);
        }
        __syncthreads();
        if ((warp >> 2) == pass) {
            int mr = (warp & 3) * 16;
#pragma unroll
            for (int hs = 0; hs < 16; hs++) {
                const uint32_t* p = Ks + (mr + lr) * FST + hs * 8 + lc;
                qf[hs][0] = p[0];
                qf[hs][1] = p[8 * FST];
                qf[hs][2] = p[4];
                qf[hs][3] = p[8 * FST + 4];
            }
        }
        __syncthreads();
    }

    float m_[2] = {-1e30f, -1e30f};
    float l_[2] = {0.f, 0.f};
    float oacc[16][4];
#pragma unroll
    for (int ns = 0; ns < 16; ns++)
#pragma unroll
        for (int j = 0; j < 4; j++) oacc[ns][j] = 0.f;

    int row0 = q0 + warp * 16 + lr;
    int njt = 2 * qt + 2;

    auto load_kv = [&](int jt, int bufsel) {
        int s0 = jt * 64;
        uint32_t* Kd = Ks + bufsel * 64 * FST;
        uint32_t* Vd = Vs + bufsel * 64 * VST;
#pragma unroll
        for (int u = 0; u < 8; u++) {
            int f = tid + 256 * u;
            int r = f >> 5, hc = (f & 31) * 4;
            size_t gofs = (((size_t)(b * T_ + s0 + r) * KH_ + kh) << 7) + hc;
            cpasync16(Kd + r * FST + hc, k + gofs);
            cpasync16(Vd + r * VST + hc, v + gofs);
        }
    };

    load_kv(0, 0);
    asm volatile("cp.async.commit_group;\n");

    for (int jt = 0; jt < njt; jt++) {
        int buf = jt & 1;
        if (jt + 1 < njt) {
            load_kv(jt + 1, buf ^ 1);
            asm volatile("cp.async.commit_group;\n");
            asm volatile("cp.async.wait_group 1;\n");
        } else {
            asm volatile("cp.async.wait_group 0;\n");
        }
        __syncthreads();

        const uint32_t* Kb = Ks + buf * 64 * FST;
        const uint32_t* Vb = Vs + buf * 64 * VST;
        int s0 = jt * 64;

        // ---- S = Q K^T ----
        float s_[8][4];
#pragma unroll
        for (int ns = 0; ns < 8; ns++)
#pragma unroll
            for (int j = 0; j < 4; j++) s_[ns][j] = 0.f;
#pragma unroll
        for (int hs = 0; hs < 16; hs++) {
#pragma unroll
            for (int ns = 0; ns < 8; ns++) {
                const uint32_t* p = Kb + (ns * 8 + lr) * FST + hs * 8 + lc;
                uint32_t bf[2] = {p[0], p[4]};
                mma_tf32(s_[ns], qf[hs], bf);
            }
        }

        // ---- causal mask (only last two kv tiles cross the diagonal) ----
        if (jt >= 2 * qt) {
#pragma unroll
            for (int ns = 0; ns < 8; ns++) {
                int col = s0 + ns * 8 + 2 * lc;
                if (col > row0)     s_[ns][0] = -1e30f;
                if (col + 1 > row0) s_[ns][1] = -1e30f;
                if (col > row0 + 8)     s_[ns][2] = -1e30f;
                if (col + 1 > row0 + 8) s_[ns][3] = -1e30f;
            }
        }

        // ---- online softmax in registers ----
        float mx0 = -1e30f, mx1 = -1e30f;
#pragma unroll
        for (int ns = 0; ns < 8; ns++) {
            mx0 = fmaxf(mx0, fmaxf(s_[ns][0], s_[ns][1]));
            mx1 = fmaxf(mx1, fmaxf(s_[ns][2], s_[ns][3]));
        }
        mx0 = fmaxf(mx0, __shfl_xor_sync(0xffffffffu, mx0, 1));
        mx0 = fmaxf(mx0, __shfl_xor_sync(0xffffffffu, mx0, 2));
        mx1 = fmaxf(mx1, __shfl_xor_sync(0xffffffffu, mx1, 1));
        mx1 = fmaxf(mx1, __shfl_xor_sync(0xffffffffu, mx1, 2));
        float mn0 = fmaxf(m_[0], mx0), mn1 = fmaxf(m_[1], mx1);
        float a0 = __expf(m_[0] - mn0), a1 = __expf(m_[1] - mn1);
        float sum0 = 0.f, sum1 = 0.f;
        uint32_t* Pw = Ps + warp * 16 * PST;
#pragma unroll
        for (int ns = 0; ns < 8; ns++) {
            float p0 = __expf(s_[ns][0] - mn0);
            float p1 = __expf(s_[ns][1] - mn0);
            float p2 = __expf(s_[ns][2] - mn1);
            float p3 = __expf(s_[ns][3] - mn1);
            sum0 += p0 + p1;
            sum1 += p2 + p3;
            *(uint2*)(Pw + lr * PST + ns * 8 + 2 * lc) =
                make_uint2(f2tf32(p0), f2tf32(p1));
            *(uint2*)(Pw + (lr + 8) * PST + ns * 8 + 2 * lc) =
                make_uint2(f2tf32(p2), f2tf32(p3));
        }
        sum0 += __shfl_xor_sync(0xffffffffu, sum0, 1);
        sum0 += __shfl_xor_sync(0xffffffffu, sum0, 2);
        sum1 += __shfl_xor_sync(0xffffffffu, sum1, 1);
        sum1 += __shfl_xor_sync(0xffffffffu, sum1, 2);
        l_[0] = l_[0] * a0 + sum0;
        l_[1] = l_[1] * a1 + sum1;
        m_[0] = mn0; m_[1] = mn1;

#pragma unroll
        for (int ns = 0; ns < 16; ns++) {
            oacc[ns][0] *= a0; oacc[ns][1] *= a0;
            oacc[ns][2] *= a1; oacc[ns][3] *= a1;
        }
        __syncwarp();

        // ---- O += P V ----
#pragma unroll
        for (int ks = 0; ks < 8; ks++) {
            const uint32_t* pp = Pw + lr * PST + ks * 8 + lc;
            uint32_t af[4] = {pp[0], pp[8 * PST], pp[4], pp[8 * PST + 4]};
#pragma unroll
            for (int ns = 0; ns < 16; ns++) {
                const uint32_t* vp = Vb + (ks * 8 + lc) * VST + ns * 8 + lr;
                uint32_t bf[2] = {vp[0], vp[4 * VST]};
                mma_tf32(oacc[ns], af, bf);
            }
        }
        __syncthreads();
    }

    // ---- epilogue: normalize + store (b,t,n,h) ----
    float inv0 = 1.f / l_[0], inv1 = 1.f / l_[1];
    size_t base0 = (((size_t)(b * T_ + row0) * NH_ + n) << 7);
    size_t base1 = (((size_t)(b * T_ + row0 + 8) * NH_ + n) << 7);
#pragma unroll
    for (int ns = 0; ns < 16; ns++) {
        int cc = ns * 8 + 2 * lc;
        *(float2*)(o + base0 + cc) = make_float2(oacc[ns][0] * inv0, oacc[ns][1] * inv0);
        *(float2*)(o + base1 + cc) = make_float2(oacc[ns][2] * inv1, oacc[ns][3] * inv1);
    }
}

// ---------------------------------------------------------------------------
extern "C" void kernel_launch(void* const* d_in, const int* in_sizes, int n_in,
                              void* d_out, int out_size) {
    const float* Xq   = (const float*)d_in[0];
    const float* Xkv  = (const float*)d_in[1];
    const int*   qpos = (const int*)  d_in[2];
    const int*   kpos = (const int*)  d_in[3];
    const float* Wq   = (const float*)d_in[4];
    const float* Wk   = (const float*)d_in[5];
    const float* Wv   = (const float*)d_in[6];
    const float* Wo   = (const float*)d_in[7];
    float* out = (float*)d_out;

    float *pq, *pk, *pv, *pa;
    cudaGetSymbolAddress((void**)&pq, g_q);
    cudaGetSymbolAddress((void**)&pk, g_k);
    cudaGetSymbolAddress((void**)&pv, g_v);
    cudaGetSymbolAddress((void**)&pa, g_attn);

    const int M = B_ * T_;  // 4096
    const float scale = 0.08838834764831845f; // 1/sqrt(128)

    // projections
    gemm_tf32<<<dim3(D_ / 128, M / 128), 256>>>(Xq, Wq, pq, M, NH_ * H_, D_);
    gemm_tf32_kv<<<dim3((KH_ * H_) / 128, M / 128, 2), 256>>>(
        Xkv, Wk, Wv, pk, pv, M, KH_ * H_, D_);

    // rope + tf32 conversion (q pre-scaled), v conversion
    rope_cvt_kernel<<<M, 64>>>(pq, qpos, NH_, scale);
    rope_cvt_kernel<<<M, 64>>>(pk, kpos, KH_, 1.0f);
    cvt_tf32_kernel<<<(B_*T_*KH_*H_) / (256 * 4), 256>>>(pv);

    // flash attention (tensor core, double-buffered)
    cudaFuncSetAttribute(flash_tc,
                         cudaFuncAttributeMaxDynamicSharedMemorySize, FA3_SMEM);
    flash_tc<<<dim3(T_ / 128, NH_, B_), 256, FA3_SMEM>>>(
        (const uint32_t*)pq, (const uint32_t*)pk, (const uint32_t*)pv, pa);

    // output projection
    gemm_tf32<<<dim3(D_ / 128, M / 128), 256>>>(pa, Wo, out, M, D_, NH_ * H_);
}